// round 1
// baseline (speedup 1.0000x reference)
#include <cuda_runtime.h>

#define EDIM   512
#define MROWS  8192        // L*B rows
#define NCHUNK 8
#define CHUNKS 256         // s-positions per stats chunk

// ---------------- scratch (no allocation allowed) ----------------
__device__ float g_q[MROWS * EDIM];
__device__ float g_k[MROWS * EDIM];
__device__ float g_v[MROWS * EDIM];
__device__ float g_a[MROWS * EDIM];
__device__ float g_part[32 * NCHUNK * 4224];  // per (head,chunk): M[64*64] + ksum[64] + vsum[64]
__device__ float g_M[32 * 4096];
__device__ float g_ksum[32 * 64];
__device__ float g_vsum[32 * 64];

// ---------------- C[M,512] = A[M,512] @ W[512,512]^T + bias -----------------
// 128x128 block tile, BK=8, double-buffered smem, 8x8 register tile per thread.
__global__ __launch_bounds__(256, 2)
void gemm_nt_kernel(const float* __restrict__ A, const float* __restrict__ W,
                    const float* __restrict__ bias, float* __restrict__ C)
{
    __shared__ float As[2][8][128];
    __shared__ float Bs[2][8][128];
    const int bm  = blockIdx.y << 7;
    const int bn  = blockIdx.x << 7;
    const int tid = threadIdx.x;
    const int lr  = tid & 127;          // tile row loaded by this thread
    const int lk  = (tid >> 7) << 2;    // k offset: 0 or 4
    const int tx  = tid & 15;
    const int ty  = tid >> 4;

    const float* ap = A + (size_t)(bm + lr) * EDIM + lk;
    const float* wp = W + (size_t)(bn + lr) * EDIM + lk;

    float4 av = *(const float4*)ap;
    float4 wv = *(const float4*)wp;
    As[0][lk+0][lr] = av.x; As[0][lk+1][lr] = av.y;
    As[0][lk+2][lr] = av.z; As[0][lk+3][lr] = av.w;
    Bs[0][lk+0][lr] = wv.x; Bs[0][lk+1][lr] = wv.y;
    Bs[0][lk+2][lr] = wv.z; Bs[0][lk+3][lr] = wv.w;
    __syncthreads();

    float acc[8][8] = {};

    for (int kt = 0; kt < 64; ++kt) {
        const int cur = kt & 1;
        if (kt < 63) {
            av = *(const float4*)(ap + (kt + 1) * 8);
            wv = *(const float4*)(wp + (kt + 1) * 8);
        }
        #pragma unroll
        for (int k = 0; k < 8; ++k) {
            float af[8], bf[8];
            *(float4*)&af[0] = *(const float4*)&As[cur][k][ty * 4];
            *(float4*)&af[4] = *(const float4*)&As[cur][k][64 + ty * 4];
            *(float4*)&bf[0] = *(const float4*)&Bs[cur][k][tx * 4];
            *(float4*)&bf[4] = *(const float4*)&Bs[cur][k][64 + tx * 4];
            #pragma unroll
            for (int i = 0; i < 8; ++i)
                #pragma unroll
                for (int j = 0; j < 8; ++j)
                    acc[i][j] += af[i] * bf[j];
        }
        if (kt < 63) {
            const int nxt = cur ^ 1;
            As[nxt][lk+0][lr] = av.x; As[nxt][lk+1][lr] = av.y;
            As[nxt][lk+2][lr] = av.z; As[nxt][lk+3][lr] = av.w;
            Bs[nxt][lk+0][lr] = wv.x; Bs[nxt][lk+1][lr] = wv.y;
            Bs[nxt][lk+2][lr] = wv.z; Bs[nxt][lk+3][lr] = wv.w;
            __syncthreads();
        }
    }

    float b0[4], b1[4];
    #pragma unroll
    for (int j = 0; j < 4; ++j) {
        b0[j] = bias[bn + tx * 4 + j];
        b1[j] = bias[bn + 64 + tx * 4 + j];
    }
    #pragma unroll
    for (int i = 0; i < 8; ++i) {
        const int m = bm + ((i < 4) ? (ty * 4 + i) : (64 + ty * 4 + i - 4));
        float4 o0, o1;
        o0.x = acc[i][0] + b0[0]; o0.y = acc[i][1] + b0[1];
        o0.z = acc[i][2] + b0[2]; o0.w = acc[i][3] + b0[3];
        o1.x = acc[i][4] + b1[0]; o1.y = acc[i][5] + b1[1];
        o1.z = acc[i][6] + b1[2]; o1.w = acc[i][7] + b1[3];
        *(float4*)(C + (size_t)m * EDIM + bn + tx * 4)      = o0;
        *(float4*)(C + (size_t)m * EDIM + bn + 64 + tx * 4) = o1;
    }
}

// ---------------- softmax over each contiguous 64-wide head group -----------
// groups are contiguous in memory: q[r*512 + h*64 ..] == flat [g*64, g*64+64)
__global__ void softmax64_kernel()
{
    const int lane = threadIdx.x & 31;
    const int warp = threadIdx.x >> 5;
    const long g = (long)blockIdx.x * 8 + warp;   // 65536 groups
    #pragma unroll
    for (int which = 0; which < 2; ++which) {
        float* p = (which ? g_k : g_q) + g * 64;
        float a = p[lane], b = p[lane + 32];
        float m = fmaxf(a, b);
        #pragma unroll
        for (int o = 16; o > 0; o >>= 1)
            m = fmaxf(m, __shfl_xor_sync(0xffffffffu, m, o));
        float ea = __expf(a - m), eb = __expf(b - m);
        float s = ea + eb;
        #pragma unroll
        for (int o = 16; o > 0; o >>= 1)
            s += __shfl_xor_sync(0xffffffffu, s, o);
        const float inv = 1.0f / s;
        p[lane]      = ea * inv;
        p[lane + 32] = eb * inv;
    }
}

// ---------------- per-head partial stats: M = K^T V, Ksum, Vsum -------------
// head n = b*8 + h; k_[n,s,d] = g_k[(s*4+b)*512 + h*64 + d]
__global__ __launch_bounds__(256)
void stats_partial_kernel()
{
    const int n = blockIdx.y;
    const int b = n >> 3, h = n & 7;
    const int s0 = blockIdx.x * CHUNKS;
    __shared__ float Ks[32][68];   // padded to kill bank conflicts
    __shared__ float Vs[32][68];
    const int tid = threadIdx.x;
    const int tx = tid & 15, ty = tid >> 4;
    const int sl = tid >> 3;
    const int dq = (tid & 7) << 3;

    float mreg[4][4] = {};
    float sreg = 0.f;

    for (int st = 0; st < CHUNKS; st += 32) {
        const int s = s0 + st + sl;
        const size_t roff = (size_t)(s * 4 + b) * EDIM + h * 64 + dq;
        const float4 k0 = *(const float4*)(g_k + roff);
        const float4 k1 = *(const float4*)(g_k + roff + 4);
        const float4 v0 = *(const float4*)(g_v + roff);
        const float4 v1 = *(const float4*)(g_v + roff + 4);
        __syncthreads();
        *(float4*)&Ks[sl][dq]     = k0;
        *(float4*)&Ks[sl][dq + 4] = k1;
        *(float4*)&Vs[sl][dq]     = v0;
        *(float4*)&Vs[sl][dq + 4] = v1;
        __syncthreads();
        #pragma unroll
        for (int ss = 0; ss < 32; ++ss) {
            float kf[4], vf[4];
            *(float4*)kf = *(const float4*)&Ks[ss][ty * 4];
            *(float4*)vf = *(const float4*)&Vs[ss][tx * 4];
            #pragma unroll
            for (int i = 0; i < 4; ++i)
                #pragma unroll
                for (int j = 0; j < 4; ++j)
                    mreg[i][j] += kf[i] * vf[j];
        }
        if (tid < 64) {
            #pragma unroll
            for (int ss = 0; ss < 32; ++ss) sreg += Ks[ss][tid];
        } else if (tid < 128) {
            #pragma unroll
            for (int ss = 0; ss < 32; ++ss) sreg += Vs[ss][tid - 64];
        }
    }
    float* pb = g_part + (size_t)(n * NCHUNK + blockIdx.x) * 4224;
    #pragma unroll
    for (int i = 0; i < 4; ++i) {
        float4 w;
        w.x = mreg[i][0]; w.y = mreg[i][1]; w.z = mreg[i][2]; w.w = mreg[i][3];
        *(float4*)(pb + (ty * 4 + i) * 64 + tx * 4) = w;
    }
    if (tid < 128) pb[4096 + tid] = sreg;   // [0..63]=ksum, [64..127]=vsum
}

__global__ void stats_reduce_kernel()
{
    const int n = blockIdx.x;
    for (int i = threadIdx.x; i < 4224; i += 256) {
        float s = 0.f;
        #pragma unroll
        for (int c = 0; c < NCHUNK; ++c)
            s += g_part[(size_t)(n * NCHUNK + c) * 4224 + i];
        if (i < 4096)       g_M[n * 4096 + i] = s;
        else if (i < 4160)  g_ksum[n * 64 + (i - 4096)] = s;
        else                g_vsum[n * 64 + (i - 4160)] = s;
    }
}

// ---------------- combine: a[r,e] = (62*Vsum + 2*q@M) / (62*2048 + 2*q.Ksum)
__global__ __launch_bounds__(256)
void combine_kernel()
{
    const int n = blockIdx.y;
    const int b = n >> 3, h = n & 7;
    const int l0 = blockIdx.x << 6;
    __shared__ float Ms[64][64];
    __shared__ float Qs[64][65];       // transposed: Qs[d][l]
    __shared__ float ksum_s[64], vsum_s[64], den_s[64];
    const int tid = threadIdx.x;

    {
        const float4* Mp = (const float4*)(g_M + (size_t)n * 4096);
        float4* Md = (float4*)&Ms[0][0];
        for (int i = tid; i < 1024; i += 256) Md[i] = Mp[i];
    }
    if (tid < 64) { ksum_s[tid] = g_ksum[n * 64 + tid]; vsum_s[tid] = g_vsum[n * 64 + tid]; }
    {
        const int l = tid >> 2;
        const int dq = (tid & 3) << 4;
        const float* qr = g_q + (size_t)((l0 + l) * 4 + b) * EDIM + h * 64 + dq;
        #pragma unroll
        for (int u = 0; u < 16; u += 4) {
            const float4 qv = *(const float4*)(qr + u);
            Qs[dq + u + 0][l] = qv.x; Qs[dq + u + 1][l] = qv.y;
            Qs[dq + u + 2][l] = qv.z; Qs[dq + u + 3][l] = qv.w;
        }
    }
    __syncthreads();
    if (tid < 64) {
        float s = 0.f;
        #pragma unroll
        for (int d = 0; d < 64; ++d) s += Qs[d][tid] * ksum_s[d];
        den_s[tid] = 1.0f / (126976.0f + 2.0f * s);   // 62*2048 = 126976
    }
    __syncthreads();
    const int tx = tid & 15, ty = tid >> 4;
    float acc[4][4] = {};
    #pragma unroll
    for (int d = 0; d < 64; ++d) {
        float qf[4], mf[4];
        #pragma unroll
        for (int i = 0; i < 4; ++i) qf[i] = Qs[d][ty * 4 + i];
        *(float4*)mf = *(const float4*)&Ms[d][tx * 4];
        #pragma unroll
        for (int i = 0; i < 4; ++i)
            #pragma unroll
            for (int j = 0; j < 4; ++j)
                acc[i][j] += qf[i] * mf[j];
    }
    #pragma unroll
    for (int i = 0; i < 4; ++i) {
        const int l = ty * 4 + i;
        const float inv = den_s[l];
        float4 o;
        o.x = (62.f * vsum_s[tx * 4 + 0] + 2.f * acc[i][0]) * inv;
        o.y = (62.f * vsum_s[tx * 4 + 1] + 2.f * acc[i][1]) * inv;
        o.z = (62.f * vsum_s[tx * 4 + 2] + 2.f * acc[i][2]) * inv;
        o.w = (62.f * vsum_s[tx * 4 + 3] + 2.f * acc[i][3]) * inv;
        *(float4*)(g_a + (size_t)((l0 + l) * 4 + b) * EDIM + h * 64 + tx * 4) = o;
    }
}

// ---------------- launch -----------------------------------------------------
extern "C" void kernel_launch(void* const* d_in, const int* in_sizes, int n_in,
                              void* d_out, int out_size)
{
    const float* query = (const float*)d_in[0];
    const float* Wq = (const float*)d_in[1];
    const float* bq = (const float*)d_in[2];
    const float* Wk = (const float*)d_in[3];
    const float* bk = (const float*)d_in[4];
    const float* Wv = (const float*)d_in[5];
    const float* bv = (const float*)d_in[6];
    const float* Wo = (const float*)d_in[7];
    const float* bo = (const float*)d_in[8];
    float* out = (float*)d_out;

    float *qp, *kp, *vp, *ap;
    cudaGetSymbolAddress((void**)&qp, g_q);
    cudaGetSymbolAddress((void**)&kp, g_k);
    cudaGetSymbolAddress((void**)&vp, g_v);
    cudaGetSymbolAddress((void**)&ap, g_a);

    const dim3 gg(4, 64), gb(256);
    gemm_nt_kernel<<<gg, gb>>>(query, Wq, bq, qp);
    gemm_nt_kernel<<<gg, gb>>>(query, Wk, bk, kp);
    gemm_nt_kernel<<<gg, gb>>>(query, Wv, bv, vp);
    softmax64_kernel<<<8192, 256>>>();
    stats_partial_kernel<<<dim3(NCHUNK, 32), 256>>>();
    stats_reduce_kernel<<<32, 256>>>();
    combine_kernel<<<dim3(32, 32), 256>>>();
    gemm_nt_kernel<<<gg, gb>>>(ap, Wo, bo, out);
}

// round 4
// speedup vs baseline: 1.4386x; 1.4386x over previous
#include <cuda_runtime.h>
#include <cuda_bf16.h>
#include <cstdint>

#define EDIM   512
#define MROWS  8192
#define NCHUNK 8
#define CHUNKS 256

// ---------------- scratch (no allocation allowed) ----------------
__device__ float g_q[MROWS * EDIM];
__device__ float g_k[MROWS * EDIM];
__device__ float g_v[MROWS * EDIM];
__device__ float g_a[MROWS * EDIM];
__device__ float g_part[32 * NCHUNK * 4224];
__device__ float g_M[32 * 4096];
__device__ float g_ksum[32 * 64];
__device__ float g_vsum[32 * 64];

// =================== helpers ===================
__device__ __forceinline__ uint32_t smem_u32(const void* p) {
    uint32_t a;
    asm("{ .reg .u64 t; cvta.to.shared.u64 t, %1; cvt.u32.u64 %0, t; }" : "=r"(a) : "l"(p));
    return a;
}
__device__ __forceinline__ uint32_t sw128(uint32_t off) { return off ^ ((off >> 3) & 0x70); }

// split a pair of fp32 into packed hi/lo bf16x2
__device__ __forceinline__ void split2(float a, float b, uint32_t& hi, uint32_t& lo) {
    __nv_bfloat16 ha = __float2bfloat16_rn(a), hb = __float2bfloat16_rn(b);
    float ra = a - __bfloat162float(ha);
    float rb = b - __bfloat162float(hb);
    __nv_bfloat16 la = __float2bfloat16_rn(ra), lb = __float2bfloat16_rn(rb);
    hi = (uint32_t)__bfloat16_as_ushort(ha) | ((uint32_t)__bfloat16_as_ushort(hb) << 16);
    lo = (uint32_t)__bfloat16_as_ushort(la) | ((uint32_t)__bfloat16_as_ushort(lb) << 16);
}
#define STSV4(addr, a0, a1, a2, a3) \
    asm volatile("st.shared.v4.b32 [%0], {%1,%2,%3,%4};" :: "r"(addr), "r"(a0), "r"(a1), "r"(a2), "r"(a3) : "memory")
#define LDSM4(r, addr) \
    asm volatile("ldmatrix.sync.aligned.m8n8.x4.shared.b16 {%0,%1,%2,%3}, [%4];" \
        : "=r"((r)[0]), "=r"((r)[1]), "=r"((r)[2]), "=r"((r)[3]) : "r"(addr))
#define MMA16816(d, a, b0, b1) \
    asm volatile("mma.sync.aligned.m16n8k16.row.col.f32.bf16.bf16.f32 " \
        "{%0,%1,%2,%3},{%4,%5,%6,%7},{%8,%9},{%0,%1,%2,%3};" \
        : "+f"((d)[0]), "+f"((d)[1]), "+f"((d)[2]), "+f"((d)[3]) \
        : "r"((a)[0]), "r"((a)[1]), "r"((a)[2]), "r"((a)[3]), "r"(b0), "r"(b1))

// ======== warp-MMA GEMM: C[8192,512] = A @ W^T + bias (fp32 via bf16 hi/lo) =====
// tile 128x128, BK=64, double-buffered SW128 smem. grid (4,64), 256 threads.
#define STAGE_BYTES 65536
#define SMEM_DYN (1024 + 2 * STAGE_BYTES)

extern __shared__ __align__(1024) char dynsmem[];

__device__ __forceinline__ void fill_stage(const float* __restrict__ Ab,
                                           const float* __restrict__ Wb,
                                           uint32_t ah, uint32_t al,
                                           uint32_t bh, uint32_t bl, int tid)
{
    #pragma unroll
    for (int it = 0; it < 4; ++it) {
        const int g = tid + it * 256;   // 0..1023
        const int r = g >> 3;           // row 0..127
        const int cg = g & 7;           // 8-col group (of 8 floats)
        const uint32_t off = sw128((uint32_t)(r * 128 + cg * 16));
        {
            const float4* src = (const float4*)(Ab + (size_t)r * EDIM + cg * 8);
            const float4 x0 = src[0], x1 = src[1];
            uint32_t h0, h1, h2, h3, l0, l1, l2, l3;
            split2(x0.x, x0.y, h0, l0); split2(x0.z, x0.w, h1, l1);
            split2(x1.x, x1.y, h2, l2); split2(x1.z, x1.w, h3, l3);
            STSV4(ah + off, h0, h1, h2, h3);
            STSV4(al + off, l0, l1, l2, l3);
        }
        {
            const float4* src = (const float4*)(Wb + (size_t)r * EDIM + cg * 8);
            const float4 x0 = src[0], x1 = src[1];
            uint32_t h0, h1, h2, h3, l0, l1, l2, l3;
            split2(x0.x, x0.y, h0, l0); split2(x0.z, x0.w, h1, l1);
            split2(x1.x, x1.y, h2, l2); split2(x1.z, x1.w, h3, l3);
            STSV4(bh + off, h0, h1, h2, h3);
            STSV4(bl + off, l0, l1, l2, l3);
        }
    }
}

__global__ __launch_bounds__(256, 1)
void gemm_tc(const float* __restrict__ A, const float* __restrict__ W,
             const float* __restrict__ bias, float* __restrict__ C)
{
    const uint32_t sbase = (smem_u32(dynsmem) + 1023u) & ~1023u;
    const int tid = threadIdx.x;
    const int wid = tid >> 5, lid = tid & 31;
    const int warp_m = wid >> 2;       // 0..1  (64 rows each)
    const int warp_n = wid & 3;        // 0..3  (32 cols each)
    const int bm = blockIdx.y << 7, bn = blockIdx.x << 7;

    float acc[4][4][4] = {};

    // lane-invariant parts of ldmatrix addresses
    // A (row-major m x k): matrices (m0-7,k0-7),(m8-15,k0-7),(m0-7,k8-15),(m8-15,k8-15)
    const int a_row = warp_m * 64 + (lid & 7) + ((lid >> 3) & 1) * 8;  // + mt*16
    const int a_kb  = (lid >> 4) * 16;                                  // + ks*32
    // B stored [n][k] = col-major k x n: matrices (n0-7,k0-7),(n0-7,k8-15),(n8-15,k0-7),(n8-15,k8-15)
    const int b_row = warp_n * 32 + (lid & 7) + (lid >> 4) * 8;         // + np*16
    const int b_kb  = ((lid >> 3) & 1) * 16;                            // + ks*32

    const uint32_t BUF = sbase;
    {
        const uint32_t ah = BUF;
        fill_stage(A + (size_t)bm * EDIM, W + (size_t)bn * EDIM,
                   ah, ah + 16384, ah + 32768, ah + 49152, tid);
    }
    __syncthreads();

    for (int c = 0; c < 8; ++c) {
        const uint32_t ah = BUF + (c & 1) * STAGE_BYTES;
        const uint32_t al = ah + 16384, bh = ah + 32768, bl = ah + 49152;

        if (c < 7) {
            const uint32_t nh = BUF + ((c + 1) & 1) * STAGE_BYTES;
            fill_stage(A + (size_t)bm * EDIM + (c + 1) * 64,
                       W + (size_t)bn * EDIM + (c + 1) * 64,
                       nh, nh + 16384, nh + 32768, nh + 49152, tid);
        }

        #pragma unroll
        for (int ks = 0; ks < 4; ++ks) {
            uint32_t Ah[4][4], Al[4][4];
            #pragma unroll
            for (int mt = 0; mt < 4; ++mt) {
                const uint32_t off = sw128((uint32_t)((a_row + mt * 16) * 128 + ks * 32 + a_kb));
                LDSM4(Ah[mt], ah + off);
                LDSM4(Al[mt], al + off);
            }
            uint32_t Bh[8], Bl[8];
            #pragma unroll
            for (int np = 0; np < 2; ++np) {
                const uint32_t off = sw128((uint32_t)((b_row + np * 16) * 128 + ks * 32 + b_kb));
                LDSM4(&Bh[np * 4], bh + off);
                LDSM4(&Bl[np * 4], bl + off);
            }
            #pragma unroll
            for (int mt = 0; mt < 4; ++mt)
                #pragma unroll
                for (int nt = 0; nt < 4; ++nt) {
                    MMA16816(acc[mt][nt], Ah[mt], Bh[nt * 2], Bh[nt * 2 + 1]);
                    MMA16816(acc[mt][nt], Ah[mt], Bl[nt * 2], Bl[nt * 2 + 1]);
                    MMA16816(acc[mt][nt], Al[mt], Bh[nt * 2], Bh[nt * 2 + 1]);
                }
        }
        __syncthreads();
    }

    // epilogue: c0,c1 @ (row lid>>2, col (lid&3)*2), c2,c3 @ row+8
    #pragma unroll
    for (int mt = 0; mt < 4; ++mt) {
        const int r0 = bm + warp_m * 64 + mt * 16 + (lid >> 2);
        #pragma unroll
        for (int nt = 0; nt < 4; ++nt) {
            const int col = bn + warp_n * 32 + nt * 8 + ((lid & 3) << 1);
            const float b0 = bias[col], b1 = bias[col + 1];
            float2 o0 = make_float2(acc[mt][nt][0] + b0, acc[mt][nt][1] + b1);
            float2 o1 = make_float2(acc[mt][nt][2] + b0, acc[mt][nt][3] + b1);
            *(float2*)(C + (size_t)r0 * EDIM + col)       = o0;
            *(float2*)(C + (size_t)(r0 + 8) * EDIM + col) = o1;
        }
    }
}

// ---------------- softmax over each contiguous 64-wide head group -----------
__global__ void softmax64_kernel()
{
    const int lane = threadIdx.x & 31;
    const int warp = threadIdx.x >> 5;
    const long g = (long)blockIdx.x * 8 + warp;
    #pragma unroll
    for (int which = 0; which < 2; ++which) {
        float* p = (which ? g_k : g_q) + g * 64;
        float a = p[lane], b = p[lane + 32];
        float m = fmaxf(a, b);
        #pragma unroll
        for (int o = 16; o > 0; o >>= 1)
            m = fmaxf(m, __shfl_xor_sync(0xffffffffu, m, o));
        float ea = __expf(a - m), eb = __expf(b - m);
        float s = ea + eb;
        #pragma unroll
        for (int o = 16; o > 0; o >>= 1)
            s += __shfl_xor_sync(0xffffffffu, s, o);
        const float inv = 1.0f / s;
        p[lane]      = ea * inv;
        p[lane + 32] = eb * inv;
    }
}

// ---------------- per-head partial stats: M = K^T V, Ksum, Vsum -------------
__global__ __launch_bounds__(256)
void stats_partial_kernel()
{
    const int n = blockIdx.y;
    const int b = n >> 3, h = n & 7;
    const int s0 = blockIdx.x * CHUNKS;
    __shared__ float Ks[32][68];
    __shared__ float Vs[32][68];
    const int tid = threadIdx.x;
    const int tx = tid & 15, ty = tid >> 4;
    const int sl = tid >> 3;
    const int dq = (tid & 7) << 3;

    float mreg[4][4] = {};
    float sreg = 0.f;

    for (int st = 0; st < CHUNKS; st += 32) {
        const int s = s0 + st + sl;
        const size_t roff = (size_t)(s * 4 + b) * EDIM + h * 64 + dq;
        const float4 k0 = *(const float4*)(g_k + roff);
        const float4 k1 = *(const float4*)(g_k + roff + 4);
        const float4 v0 = *(const float4*)(g_v + roff);
        const float4 v1 = *(const float4*)(g_v + roff + 4);
        __syncthreads();
        *(float4*)&Ks[sl][dq]     = k0;
        *(float4*)&Ks[sl][dq + 4] = k1;
        *(float4*)&Vs[sl][dq]     = v0;
        *(float4*)&Vs[sl][dq + 4] = v1;
        __syncthreads();
        #pragma unroll
        for (int ss = 0; ss < 32; ++ss) {
            float kf[4], vf[4];
            *(float4*)kf = *(const float4*)&Ks[ss][ty * 4];
            *(float4*)vf = *(const float4*)&Vs[ss][tx * 4];
            #pragma unroll
            for (int i = 0; i < 4; ++i)
                #pragma unroll
                for (int j = 0; j < 4; ++j)
                    mreg[i][j] += kf[i] * vf[j];
        }
        if (tid < 64) {
            #pragma unroll
            for (int ss = 0; ss < 32; ++ss) sreg += Ks[ss][tid];
        } else if (tid < 128) {
            #pragma unroll
            for (int ss = 0; ss < 32; ++ss) sreg += Vs[ss][tid - 64];
        }
    }
    float* pb = g_part + (size_t)(n * NCHUNK + blockIdx.x) * 4224;
    #pragma unroll
    for (int i = 0; i < 4; ++i) {
        float4 w;
        w.x = mreg[i][0]; w.y = mreg[i][1]; w.z = mreg[i][2]; w.w = mreg[i][3];
        *(float4*)(pb + (ty * 4 + i) * 64 + tx * 4) = w;
    }
    if (tid < 128) pb[4096 + tid] = sreg;
}

__global__ void stats_reduce_kernel()
{
    const int n = blockIdx.x;
    for (int i = threadIdx.x; i < 4224; i += 256) {
        float s = 0.f;
        #pragma unroll
        for (int c = 0; c < NCHUNK; ++c)
            s += g_part[(size_t)(n * NCHUNK + c) * 4224 + i];
        if (i < 4096)       g_M[n * 4096 + i] = s;
        else if (i < 4160)  g_ksum[n * 64 + (i - 4096)] = s;
        else                g_vsum[n * 64 + (i - 4160)] = s;
    }
}

// ---------------- combine: a = (62*Vsum + 2*q@M) / (62*2048 + 2*q.Ksum) -----
__global__ __launch_bounds__(256)
void combine_kernel()
{
    const int n = blockIdx.y;
    const int b = n >> 3, h = n & 7;
    const int l0 = blockIdx.x << 6;
    __shared__ float Ms[64][64];
    __shared__ float Qs[64][65];
    __shared__ float ksum_s[64], vsum_s[64], den_s[64];
    const int tid = threadIdx.x;

    {
        const float4* Mp = (const float4*)(g_M + (size_t)n * 4096);
        float4* Md = (float4*)&Ms[0][0];
        for (int i = tid; i < 1024; i += 256) Md[i] = Mp[i];
    }
    if (tid < 64) { ksum_s[tid] = g_ksum[n * 64 + tid]; vsum_s[tid] = g_vsum[n * 64 + tid]; }
    {
        const int l = tid >> 2;
        const int dq = (tid & 3) << 4;
        const float* qr = g_q + (size_t)((l0 + l) * 4 + b) * EDIM + h * 64 + dq;
        #pragma unroll
        for (int u = 0; u < 16; u += 4) {
            const float4 qv = *(const float4*)(qr + u);
            Qs[dq + u + 0][l] = qv.x; Qs[dq + u + 1][l] = qv.y;
            Qs[dq + u + 2][l] = qv.z; Qs[dq + u + 3][l] = qv.w;
        }
    }
    __syncthreads();
    if (tid < 64) {
        float s = 0.f;
        #pragma unroll
        for (int d = 0; d < 64; ++d) s += Qs[d][tid] * ksum_s[d];
        den_s[tid] = 1.0f / (126976.0f + 2.0f * s);
    }
    __syncthreads();
    const int tx = tid & 15, ty = tid >> 4;
    float acc[4][4] = {};
    #pragma unroll
    for (int d = 0; d < 64; ++d) {
        float qf[4], mf[4];
        #pragma unroll
        for (int i = 0; i < 4; ++i) qf[i] = Qs[d][ty * 4 + i];
        *(float4*)mf = *(const float4*)&Ms[d][tx * 4];
        #pragma unroll
        for (int i = 0; i < 4; ++i)
            #pragma unroll
            for (int j = 0; j < 4; ++j)
                acc[i][j] += qf[i] * mf[j];
    }
    #pragma unroll
    for (int i = 0; i < 4; ++i) {
        const int l = ty * 4 + i;
        const float inv = den_s[l];
        float4 o;
        o.x = (62.f * vsum_s[tx * 4 + 0] + 2.f * acc[i][0]) * inv;
        o.y = (62.f * vsum_s[tx * 4 + 1] + 2.f * acc[i][1]) * inv;
        o.z = (62.f * vsum_s[tx * 4 + 2] + 2.f * acc[i][2]) * inv;
        o.w = (62.f * vsum_s[tx * 4 + 3] + 2.f * acc[i][3]) * inv;
        *(float4*)(g_a + (size_t)((l0 + l) * 4 + b) * EDIM + h * 64 + tx * 4) = o;
    }
}

// ---------------- launch -----------------------------------------------------
extern "C" void kernel_launch(void* const* d_in, const int* in_sizes, int n_in,
                              void* d_out, int out_size)
{
    const float* query = (const float*)d_in[0];
    const float* Wq = (const float*)d_in[1];
    const float* bq = (const float*)d_in[2];
    const float* Wk = (const float*)d_in[3];
    const float* bk = (const float*)d_in[4];
    const float* Wv = (const float*)d_in[5];
    const float* bv = (const float*)d_in[6];
    const float* Wo = (const float*)d_in[7];
    const float* bo = (const float*)d_in[8];
    float* out = (float*)d_out;

    float *qp, *kp, *vp, *ap;
    cudaGetSymbolAddress((void**)&qp, g_q);
    cudaGetSymbolAddress((void**)&kp, g_k);
    cudaGetSymbolAddress((void**)&vp, g_v);
    cudaGetSymbolAddress((void**)&ap, g_a);

    cudaFuncSetAttribute(gemm_tc, cudaFuncAttributeMaxDynamicSharedMemorySize, SMEM_DYN);

    const dim3 gg(4, 64), gb(256);
    gemm_tc<<<gg, gb, SMEM_DYN>>>(query, Wq, bq, qp);
    gemm_tc<<<gg, gb, SMEM_DYN>>>(query, Wk, bk, kp);
    gemm_tc<<<gg, gb, SMEM_DYN>>>(query, Wv, bv, vp);
    softmax64_kernel<<<8192, 256>>>();
    stats_partial_kernel<<<dim3(NCHUNK, 32), 256>>>();
    stats_reduce_kernel<<<32, 256>>>();
    combine_kernel<<<dim3(32, 32), 256>>>();
    gemm_tc<<<gg, gb, SMEM_DYN>>>(ap, Wo, bo, out);
}

// round 5
// speedup vs baseline: 2.1005x; 1.4601x over previous
#include <cuda_runtime.h>
#include <cuda_bf16.h>
#include <cstdint>

#define EDIM   512
#define MROWS  8192
#define NCHUNK 8
#define CHUNKS 256

// ---------------- scratch (no allocation allowed) ----------------
__device__ float g_q[MROWS * EDIM];
__device__ float g_k[MROWS * EDIM];
__device__ float g_v[MROWS * EDIM];
__device__ float g_part[32 * NCHUNK * 4224];
__device__ float g_M[32 * 4096];
__device__ float g_ksum[32 * 64];
__device__ float g_vsum[32 * 64];
// bf16 hi/lo operands
__device__ __nv_bfloat16 g_xh[MROWS * EDIM];   // query hi
__device__ __nv_bfloat16 g_xl[MROWS * EDIM];   // query lo
__device__ __nv_bfloat16 g_wh[4 * EDIM * EDIM]; // Wq|Wk|Wv|Wo hi (2048 rows)
__device__ __nv_bfloat16 g_wl[4 * EDIM * EDIM];
__device__ __nv_bfloat16 g_ah[MROWS * EDIM];   // attention-out hi
__device__ __nv_bfloat16 g_al[MROWS * EDIM];
__device__ float g_bp[4 * EDIM];               // packed biases

// =================== helpers ===================
__device__ __forceinline__ uint32_t smem_u32(const void* p) {
    uint32_t a;
    asm("{ .reg .u64 t; cvta.to.shared.u64 t, %1; cvt.u32.u64 %0, t; }" : "=r"(a) : "l"(p));
    return a;
}
__device__ __forceinline__ uint32_t sw128(uint32_t off) { return off ^ ((off >> 3) & 0x70); }

__device__ __forceinline__ void split2(float a, float b, uint32_t& hi, uint32_t& lo) {
    __nv_bfloat16 ha = __float2bfloat16_rn(a), hb = __float2bfloat16_rn(b);
    float ra = a - __bfloat162float(ha);
    float rb = b - __bfloat162float(hb);
    __nv_bfloat16 la = __float2bfloat16_rn(ra), lb = __float2bfloat16_rn(rb);
    hi = (uint32_t)__bfloat16_as_ushort(ha) | ((uint32_t)__bfloat16_as_ushort(hb) << 16);
    lo = (uint32_t)__bfloat16_as_ushort(la) | ((uint32_t)__bfloat16_as_ushort(lb) << 16);
}
#define LDSM4(r, addr) \
    asm volatile("ldmatrix.sync.aligned.m8n8.x4.shared.b16 {%0,%1,%2,%3}, [%4];" \
        : "=r"((r)[0]), "=r"((r)[1]), "=r"((r)[2]), "=r"((r)[3]) : "r"(addr))
#define MMA16816(d, a, b0, b1) \
    asm volatile("mma.sync.aligned.m16n8k16.row.col.f32.bf16.bf16.f32 " \
        "{%0,%1,%2,%3},{%4,%5,%6,%7},{%8,%9},{%0,%1,%2,%3};" \
        : "+f"((d)[0]), "+f"((d)[1]), "+f"((d)[2]), "+f"((d)[3]) \
        : "r"((a)[0]), "r"((a)[1]), "r"((a)[2]), "r"((a)[3]), "r"(b0), "r"(b1))
#define CP16(saddr, gptr) \
    asm volatile("cp.async.cg.shared.global [%0], [%1], 16;" :: "r"(saddr), "l"(gptr))
#define CP_COMMIT() asm volatile("cp.async.commit_group;" ::: "memory")
#define CP_WAIT1()  asm volatile("cp.async.wait_group 1;" ::: "memory")
#define CP_WAIT0()  asm volatile("cp.async.wait_group 0;" ::: "memory")

// ---------------- fp32 -> bf16 hi/lo split (elementwise) ----------------
__global__ void split_kernel(const float4* __restrict__ src,
                             uint2* __restrict__ dh, uint2* __restrict__ dl, int n4)
{
    const int i = blockIdx.x * blockDim.x + threadIdx.x;
    if (i >= n4) return;
    const float4 x = src[i];
    uint32_t h0, h1, l0, l1;
    split2(x.x, x.y, h0, l0);
    split2(x.z, x.w, h1, l1);
    dh[i] = make_uint2(h0, h1);
    dl[i] = make_uint2(l0, l1);
}

__global__ void pack_bias_kernel(const float* __restrict__ bq, const float* __restrict__ bk,
                                 const float* __restrict__ bv, const float* __restrict__ bo)
{
    const int i = blockIdx.x * blockDim.x + threadIdx.x;
    if (i < EDIM) {
        g_bp[i] = bq[i];
        g_bp[EDIM + i] = bk[i];
        g_bp[2 * EDIM + i] = bv[i];
        g_bp[3 * EDIM + i] = bo[i];
    }
}

// ======== bf16 3-pass warp-MMA GEMM, cp.async 2-stage pipeline ========
// C[*, n-tile] = A @ W^T + bias. tile 128x128, BK=64. grid (ntiles, 64), 256 thr.
#define STAGE_BYTES 65536
#define SMEM_DYN (2 * STAGE_BYTES)

extern __shared__ __align__(1024) char dynsmem[];

__global__ __launch_bounds__(256, 1)
void gemm_bf16(const __nv_bfloat16* __restrict__ Ah, const __nv_bfloat16* __restrict__ Al,
               int wbase, float* __restrict__ out0, float* __restrict__ out1,
               float* __restrict__ out2)
{
    const uint32_t sbase = smem_u32(dynsmem);
    const int tid = threadIdx.x;
    const int wid = tid >> 5, lid = tid & 31;
    const int warp_m = wid >> 2;
    const int warp_n = wid & 3;
    const int nb = blockIdx.x;
    const int bm = blockIdx.y << 7;
    const int bn = (nb & 3) << 7;
    const int sel = nb >> 2;
    float* outp = (sel == 0) ? out0 : ((sel == 1) ? out1 : out2);
    const int wrow = wbase + nb * 128;

    // per-thread copy coords (4 chunks per buffer)
    int cp_r[4], cp_cg[4];
    uint32_t cp_soff[4];
    #pragma unroll
    for (int it = 0; it < 4; ++it) {
        const int g = tid + it * 256;
        cp_r[it] = g >> 3;
        cp_cg[it] = g & 7;
        cp_soff[it] = sw128((uint32_t)(cp_r[it] * 128 + cp_cg[it] * 16));
    }

    float acc[4][4][4] = {};
    const int a_row = warp_m * 64 + (lid & 7) + ((lid >> 3) & 1) * 8;
    const int a_kb  = (lid >> 4) * 16;
    const int b_row = warp_n * 32 + (lid & 7) + (lid >> 4) * 8;
    const int b_kb  = ((lid >> 3) & 1) * 16;

    // issue stage c into buffer buf
    auto issue = [&](int c, int buf) {
        const uint32_t ah = sbase + buf * STAGE_BYTES;
        const uint32_t al = ah + 16384, bh = ah + 32768, bl = ah + 49152;
        const int kof = c * 64;
        #pragma unroll
        for (int it = 0; it < 4; ++it) {
            const size_t aoff = (size_t)(bm + cp_r[it]) * EDIM + kof + cp_cg[it] * 8;
            const size_t boff = (size_t)(wrow + cp_r[it]) * EDIM + kof + cp_cg[it] * 8;
            CP16(ah + cp_soff[it], Ah + aoff);
            CP16(al + cp_soff[it], Al + aoff);
            CP16(bh + cp_soff[it], g_wh + boff);
            CP16(bl + cp_soff[it], g_wl + boff);
        }
        CP_COMMIT();
    };

    issue(0, 0);

    for (int c = 0; c < 8; ++c) {
        if (c < 7) { issue(c + 1, (c + 1) & 1); CP_WAIT1(); }
        else       { CP_WAIT0(); }
        __syncthreads();

        const uint32_t ah = sbase + (c & 1) * STAGE_BYTES;
        const uint32_t al = ah + 16384, bh = ah + 32768, bl = ah + 49152;

        #pragma unroll
        for (int ks = 0; ks < 4; ++ks) {
            uint32_t Ahf[4][4], Alf[4][4];
            #pragma unroll
            for (int mt = 0; mt < 4; ++mt) {
                const uint32_t off = sw128((uint32_t)((a_row + mt * 16) * 128 + ks * 32 + a_kb));
                LDSM4(Ahf[mt], ah + off);
                LDSM4(Alf[mt], al + off);
            }
            uint32_t Bh[8], Bl[8];
            #pragma unroll
            for (int np = 0; np < 2; ++np) {
                const uint32_t off = sw128((uint32_t)((b_row + np * 16) * 128 + ks * 32 + b_kb));
                LDSM4(&Bh[np * 4], bh + off);
                LDSM4(&Bl[np * 4], bl + off);
            }
            #pragma unroll
            for (int mt = 0; mt < 4; ++mt)
                #pragma unroll
                for (int nt = 0; nt < 4; ++nt) {
                    MMA16816(acc[mt][nt], Ahf[mt], Bh[nt * 2], Bh[nt * 2 + 1]);
                    MMA16816(acc[mt][nt], Ahf[mt], Bl[nt * 2], Bl[nt * 2 + 1]);
                    MMA16816(acc[mt][nt], Alf[mt], Bh[nt * 2], Bh[nt * 2 + 1]);
                }
        }
        __syncthreads();
    }

    // epilogue
    #pragma unroll
    for (int mt = 0; mt < 4; ++mt) {
        const int r0 = bm + warp_m * 64 + mt * 16 + (lid >> 2);
        #pragma unroll
        for (int nt = 0; nt < 4; ++nt) {
            const int cit = warp_n * 32 + nt * 8 + ((lid & 3) << 1);
            const float b0 = g_bp[wrow + cit], b1 = g_bp[wrow + cit + 1];
            const int col = bn + cit;
            float2 o0 = make_float2(acc[mt][nt][0] + b0, acc[mt][nt][1] + b1);
            float2 o1 = make_float2(acc[mt][nt][2] + b0, acc[mt][nt][3] + b1);
            *(float2*)(outp + (size_t)r0 * EDIM + col)       = o0;
            *(float2*)(outp + (size_t)(r0 + 8) * EDIM + col) = o1;
        }
    }
}

// ---------------- softmax over each contiguous 64-wide head group -----------
__global__ void softmax64_kernel()
{
    const int lane = threadIdx.x & 31;
    const int warp = threadIdx.x >> 5;
    const long g = (long)blockIdx.x * 8 + warp;
    #pragma unroll
    for (int which = 0; which < 2; ++which) {
        float* p = (which ? g_k : g_q) + g * 64;
        float a = p[lane], b = p[lane + 32];
        float m = fmaxf(a, b);
        #pragma unroll
        for (int o = 16; o > 0; o >>= 1)
            m = fmaxf(m, __shfl_xor_sync(0xffffffffu, m, o));
        float ea = __expf(a - m), eb = __expf(b - m);
        float s = ea + eb;
        #pragma unroll
        for (int o = 16; o > 0; o >>= 1)
            s += __shfl_xor_sync(0xffffffffu, s, o);
        const float inv = 1.0f / s;
        p[lane]      = ea * inv;
        p[lane + 32] = eb * inv;
    }
}

// ---------------- per-head partial stats: M = K^T V, Ksum, Vsum -------------
__global__ __launch_bounds__(256)
void stats_partial_kernel()
{
    const int n = blockIdx.y;
    const int b = n >> 3, h = n & 7;
    const int s0 = blockIdx.x * CHUNKS;
    __shared__ float Ks[32][68];
    __shared__ float Vs[32][68];
    const int tid = threadIdx.x;
    const int tx = tid & 15, ty = tid >> 4;
    const int sl = tid >> 3;
    const int dq = (tid & 7) << 3;

    float mreg[4][4] = {};
    float sreg = 0.f;

    for (int st = 0; st < CHUNKS; st += 32) {
        const int s = s0 + st + sl;
        const size_t roff = (size_t)(s * 4 + b) * EDIM + h * 64 + dq;
        const float4 k0 = *(const float4*)(g_k + roff);
        const float4 k1 = *(const float4*)(g_k + roff + 4);
        const float4 v0 = *(const float4*)(g_v + roff);
        const float4 v1 = *(const float4*)(g_v + roff + 4);
        __syncthreads();
        *(float4*)&Ks[sl][dq]     = k0;
        *(float4*)&Ks[sl][dq + 4] = k1;
        *(float4*)&Vs[sl][dq]     = v0;
        *(float4*)&Vs[sl][dq + 4] = v1;
        __syncthreads();
        #pragma unroll
        for (int ss = 0; ss < 32; ++ss) {
            float kf[4], vf[4];
            *(float4*)kf = *(const float4*)&Ks[ss][ty * 4];
            *(float4*)vf = *(const float4*)&Vs[ss][tx * 4];
            #pragma unroll
            for (int i = 0; i < 4; ++i)
                #pragma unroll
                for (int j = 0; j < 4; ++j)
                    mreg[i][j] += kf[i] * vf[j];
        }
        if (tid < 64) {
            #pragma unroll
            for (int ss = 0; ss < 32; ++ss) sreg += Ks[ss][tid];
        } else if (tid < 128) {
            #pragma unroll
            for (int ss = 0; ss < 32; ++ss) sreg += Vs[ss][tid - 64];
        }
    }
    float* pb = g_part + (size_t)(n * NCHUNK + blockIdx.x) * 4224;
    #pragma unroll
    for (int i = 0; i < 4; ++i) {
        float4 w;
        w.x = mreg[i][0]; w.y = mreg[i][1]; w.z = mreg[i][2]; w.w = mreg[i][3];
        *(float4*)(pb + (ty * 4 + i) * 64 + tx * 4) = w;
    }
    if (tid < 128) pb[4096 + tid] = sreg;
}

__global__ void stats_reduce_kernel()
{
    const int n = blockIdx.x;
    for (int i = threadIdx.x; i < 4224; i += 256) {
        float s = 0.f;
        #pragma unroll
        for (int c = 0; c < NCHUNK; ++c)
            s += g_part[(size_t)(n * NCHUNK + c) * 4224 + i];
        if (i < 4096)       g_M[n * 4096 + i] = s;
        else if (i < 4160)  g_ksum[n * 64 + (i - 4096)] = s;
        else                g_vsum[n * 64 + (i - 4160)] = s;
    }
}

// ---- combine: a = (62*Vsum + 2*q@M) / (62*2048 + 2*q.Ksum), emit bf16 hi/lo ----
__global__ __launch_bounds__(256)
void combine_kernel()
{
    const int n = blockIdx.y;
    const int b = n >> 3, h = n & 7;
    const int l0 = blockIdx.x << 6;
    __shared__ float Ms[64][64];
    __shared__ float Qs[64][65];
    __shared__ float ksum_s[64], vsum_s[64], den_s[64];
    const int tid = threadIdx.x;

    {
        const float4* Mp = (const float4*)(g_M + (size_t)n * 4096);
        float4* Md = (float4*)&Ms[0][0];
        for (int i = tid; i < 1024; i += 256) Md[i] = Mp[i];
    }
    if (tid < 64) { ksum_s[tid] = g_ksum[n * 64 + tid]; vsum_s[tid] = g_vsum[n * 64 + tid]; }
    {
        const int l = tid >> 2;
        const int dq = (tid & 3) << 4;
        const float* qr = g_q + (size_t)((l0 + l) * 4 + b) * EDIM + h * 64 + dq;
        #pragma unroll
        for (int u = 0; u < 16; u += 4) {
            const float4 qv = *(const float4*)(qr + u);
            Qs[dq + u + 0][l] = qv.x; Qs[dq + u + 1][l] = qv.y;
            Qs[dq + u + 2][l] = qv.z; Qs[dq + u + 3][l] = qv.w;
        }
    }
    __syncthreads();
    if (tid < 64) {
        float s = 0.f;
        #pragma unroll
        for (int d = 0; d < 64; ++d) s += Qs[d][tid] * ksum_s[d];
        den_s[tid] = 1.0f / (126976.0f + 2.0f * s);
    }
    __syncthreads();
    const int tx = tid & 15, ty = tid >> 4;
    float acc[4][4] = {};
    #pragma unroll
    for (int d = 0; d < 64; ++d) {
        float qf[4], mf[4];
        #pragma unroll
        for (int i = 0; i < 4; ++i) qf[i] = Qs[d][ty * 4 + i];
        *(float4*)mf = *(const float4*)&Ms[d][tx * 4];
        #pragma unroll
        for (int i = 0; i < 4; ++i)
            #pragma unroll
            for (int j = 0; j < 4; ++j)
                acc[i][j] += qf[i] * mf[j];
    }
    #pragma unroll
    for (int i = 0; i < 4; ++i) {
        const int l = ty * 4 + i;
        const float inv = den_s[l];
        float ox = (62.f * vsum_s[tx * 4 + 0] + 2.f * acc[i][0]) * inv;
        float oy = (62.f * vsum_s[tx * 4 + 1] + 2.f * acc[i][1]) * inv;
        float oz = (62.f * vsum_s[tx * 4 + 2] + 2.f * acc[i][2]) * inv;
        float ow = (62.f * vsum_s[tx * 4 + 3] + 2.f * acc[i][3]) * inv;
        uint32_t h0, h1, lo0, lo1;
        split2(ox, oy, h0, lo0);
        split2(oz, ow, h1, lo1);
        const size_t off = (size_t)((l0 + l) * 4 + b) * EDIM + h * 64 + tx * 4;
        *(uint2*)(g_ah + off) = make_uint2(h0, h1);
        *(uint2*)(g_al + off) = make_uint2(lo0, lo1);
    }
}

// ---------------- launch -----------------------------------------------------
extern "C" void kernel_launch(void* const* d_in, const int* in_sizes, int n_in,
                              void* d_out, int out_size)
{
    const float* query = (const float*)d_in[0];
    const float* Wq = (const float*)d_in[1];
    const float* bq = (const float*)d_in[2];
    const float* Wk = (const float*)d_in[3];
    const float* bk = (const float*)d_in[4];
    const float* Wv = (const float*)d_in[5];
    const float* bv = (const float*)d_in[6];
    const float* Wo = (const float*)d_in[7];
    const float* bo = (const float*)d_in[8];
    float* out = (float*)d_out;

    float *qp, *kp, *vp;
    __nv_bfloat16 *xh, *xl, *wh, *wl, *ahp, *alp;
    cudaGetSymbolAddress((void**)&qp, g_q);
    cudaGetSymbolAddress((void**)&kp, g_k);
    cudaGetSymbolAddress((void**)&vp, g_v);
    cudaGetSymbolAddress((void**)&xh, g_xh);
    cudaGetSymbolAddress((void**)&xl, g_xl);
    cudaGetSymbolAddress((void**)&wh, g_wh);
    cudaGetSymbolAddress((void**)&wl, g_wl);
    cudaGetSymbolAddress((void**)&ahp, g_ah);
    cudaGetSymbolAddress((void**)&alp, g_al);

    cudaFuncSetAttribute(gemm_bf16, cudaFuncAttributeMaxDynamicSharedMemorySize, SMEM_DYN);

    // convert inputs
    const int nq4 = MROWS * EDIM / 4;
    split_kernel<<<(nq4 + 255) / 256, 256>>>((const float4*)query, (uint2*)xh, (uint2*)xl, nq4);
    const int nw4 = EDIM * EDIM / 4;
    split_kernel<<<(nw4 + 255) / 256, 256>>>((const float4*)Wq, (uint2*)wh, (uint2*)wl, nw4);
    split_kernel<<<(nw4 + 255) / 256, 256>>>((const float4*)Wk, (uint2*)(wh + EDIM * EDIM / 4 * 4),
                                             (uint2*)(wl + EDIM * EDIM), nw4);
    split_kernel<<<(nw4 + 255) / 256, 256>>>((const float4*)Wv, (uint2*)(wh + 2 * EDIM * EDIM),
                                             (uint2*)(wl + 2 * EDIM * EDIM), nw4);
    split_kernel<<<(nw4 + 255) / 256, 256>>>((const float4*)Wo, (uint2*)(wh + 3 * EDIM * EDIM),
                                             (uint2*)(wl + 3 * EDIM * EDIM), nw4);
    pack_bias_kernel<<<2, 256>>>(bq, bk, bv, bo);

    // fused QKV GEMM
    gemm_bf16<<<dim3(12, 64), 256, SMEM_DYN>>>(xh, xl, 0, qp, kp, vp);
    softmax64_kernel<<<8192, 256>>>();
    stats_partial_kernel<<<dim3(NCHUNK, 32), 256>>>();
    stats_reduce_kernel<<<32, 256>>>();
    combine_kernel<<<dim3(32, 32), 256>>>();
    // O GEMM
    gemm_bf16<<<dim3(4, 64), 256, SMEM_DYN>>>(ahp, alp, 3 * EDIM, out, out, out);
}